// round 10
// baseline (speedup 1.0000x reference)
#include <cuda_runtime.h>
#include <cstdint>

#define Bb 32
#define Ss 256
#define Ll 64
#define Dd 100
#define Mm 20
#define NSLOT (Bb * Mm)   // 640
#define NSM   148
#define NBLK  (2 * NSM)   // 296: blocks bid and bid+148 co-reside (LUT_classic[bid%148])

typedef unsigned long long ULL;

// ---------------- scratch (no allocations allowed) ----------------
__device__ __align__(16) float  g_enc [Bb * Ss * Dd];      // [B,S,D]
__device__ __align__(16) float2 g_esw [Bb * Ss * Dd];      // [B,S,D] (enc, enc@W^T)
__device__ __align__(16) float  g_kg  [Bb * Ss * Mm];      // [B,S,M] enc . keys[m]

// ---------------- helpers ----------------
__device__ __forceinline__ void fma2(ULL& acc, ULL a, ULL b) {
    asm("fma.rn.f32x2 %0, %1, %2, %0;" : "+l"(acc) : "l"(a), "l"(b));
}
__device__ __forceinline__ ULL pack2(float lo, float hi) {
    ULL r;
    asm("mov.b64 %0, {%1, %2};" : "=l"(r) : "f"(lo), "f"(hi));
    return r;
}
__device__ __forceinline__ float sum2(ULL v) {
    float lo, hi;
    asm("mov.b64 {%0, %1}, %2;" : "=f"(lo), "=f"(hi) : "l"(v));
    return lo + hi;
}

// ================= K1: encode (float4 path) =================
__global__ void k_encode(const float4* __restrict__ batch4,
                         const float4* __restrict__ mult4,
                         float4* __restrict__ enc4) {
    __shared__ float4 sm4[100];
    int row = blockIdx.x;           // b*S + s
    int t = threadIdx.x;

    if (t < 100) {
        int c  = t % 25;
        int lg = t / 25;
        const float4* bp = batch4 + (size_t)row * (Ll * 25);
        float4 acc = make_float4(0.f, 0.f, 0.f, 0.f);
#pragma unroll
        for (int k = 0; k < 16; ++k) {
            int l = lg + 4 * k;
            float4 bv = bp[l * 25 + c];
            float4 mv = __ldg(&mult4[l * 25 + c]);
            acc.x += bv.x * mv.x;
            acc.y += bv.y * mv.y;
            acc.z += bv.z * mv.z;
            acc.w += bv.w * mv.w;
        }
        sm4[t] = acc;
    }
    __syncthreads();
    if (t < 25) {
        float4 a = sm4[t], b = sm4[t + 25], c = sm4[t + 50], d = sm4[t + 75];
        float4 r;
        r.x = (a.x + b.x) + (c.x + d.x);
        r.y = (a.y + b.y) + (c.y + d.y);
        r.z = (a.z + b.z) + (c.z + d.z);
        r.w = (a.w + b.w) + (c.w + d.w);
        enc4[(size_t)row * 25 + t] = r;
    }
}

// ================= K2: project -> g_esw=(enc, enc@W^T), g_kg =================
#define R2 16
__global__ void k_project(const float* __restrict__ W,
                          const float* __restrict__ keys) {
    __shared__ float Wt[Dd * Dd];        // Wt[d*Dd + e] = W[e*Dd + d]
    __shared__ float encs[R2][Dd];
    int t = threadIdx.x;
    int row0 = blockIdx.x * R2;

    for (int idx = t; idx < Dd * Dd; idx += blockDim.x) {
        int e = idx / Dd, d = idx % Dd;
        Wt[d * Dd + e] = W[idx];
    }
    for (int idx = t; idx < R2 * Dd; idx += blockDim.x)
        ((float*)encs)[idx] = g_enc[(size_t)row0 * Dd + idx];
    __syncthreads();

    if (t < Dd) {
        for (int r = 0; r < R2; ++r) {
            float acc = 0.f;
#pragma unroll 4
            for (int d = 0; d < Dd; ++d)
                acc += encs[r][d] * Wt[d * Dd + t];
            g_esw[(size_t)(row0 + r) * Dd + t] = make_float2(encs[r][t], acc);
        }
    } else if (t < Dd + Mm) {
        int m = t - Dd;
        for (int r = 0; r < R2; ++r) {
            float acc = 0.f;
#pragma unroll 4
            for (int d = 0; d < Dd; ++d)
                acc += encs[r][d] * __ldg(&keys[m * Dd + d]);
            g_kg[(size_t)(row0 + r) * Mm + m] = acc;
        }
    }
}

// ================= K3: scan, 128 threads, 2-3 slots, pair-balanced =================
// Pair p=bid%148 owns slots [p*640/148, (p+1)*640/148) (4 or 5); block bid<148
// takes the first ceil(n/2) (2 or 3), bid>=148 the rest (2). Both blocks of a
// pair land on the same SM (wave-1 LUT), so every SM carries 4-5 slots.
// Matvec: warp w owns d in [26w,26w+26); thread (w,lane) holds U[e,d] for
// e in {lane,+32,+64,+96}. State: thread t owns e=t. h stored NORMALIZED.
__global__ void __launch_bounds__(128, 2)
k_scan(const float* __restrict__ keys, const float* __restrict__ U,
       const float* __restrict__ V, const float* __restrict__ prelu_a,
       float* __restrict__ out) {
    __shared__ __align__(16) float hs[3][104];     // pads [100,104) = 0
    __shared__ float part[3][4][128];              // [slot][dwarp][e]
    __shared__ float  redA[3][4];                  // wp per slot per warp
    __shared__ float2 redB[3][4];                  // (hc, cc)

    int bid = blockIdx.x;
    int p = bid % NSM, half = bid / NSM;
    int p0 = (p * NSLOT) / NSM;
    int p1 = ((p + 1) * NSLOT) / NSM;
    int n = p1 - p0;                       // 4 or 5
    int nfirst = (n + 1) >> 1;             // 2 or 3
    int start = half ? p0 + nfirst : p0;
    int ns = half ? (n - nfirst) : nfirst; // 2 or 3 (block-uniform)
    bool three = (ns == 3);

    int t = threadIdx.x;
    int lane = t & 31, w = t >> 5;
    bool act = (t < Dd);
    float aprelu = __ldg(prelu_a);

    int sl[3], bb[3], mm[3];
#pragma unroll
    for (int j = 0; j < 3; ++j) {
        int s = start + (j < ns ? j : ns - 1);   // clamp (unused lanes read slot ns-1)
        sl[j] = s;
        bb[j] = s / Mm;
        mm[j] = s % Mm;
    }

    // ---- U quarter-tile: 4 e-rows x 13 d-pairs (my warp's d-range) ----
    ULL U2[4][13];
#pragma unroll
    for (int j = 0; j < 4; ++j) {
        int e = lane + 32 * j;
#pragma unroll
        for (int k = 0; k < 13; ++k) {
            int d = 26 * w + 2 * k;
            float u0 = (e < Dd && d     < Dd) ? __ldg(&U[e * Dd + d])     : 0.f;
            float u1 = (e < Dd && d + 1 < Dd) ? __ldg(&U[e * Dd + d + 1]) : 0.f;
            U2[j][k] = pack2(u0, u1);
        }
    }

    // ---- step-invariant keysV[m,e] per slot ----
    float kv[3] = {0.f, 0.f, 0.f};
    if (act) {
#pragma unroll 4
        for (int d = 0; d < Dd; ++d) {
            float ve = __ldg(&V[t * Dd + d]);
            kv[0] += __ldg(&keys[mm[0] * Dd + d]) * ve;
            kv[1] += __ldg(&keys[mm[1] * Dd + d]) * ve;
            if (three) kv[2] += __ldg(&keys[mm[2] * Dd + d]) * ve;
        }
    }

    // ---- init: h = raw keys; hh = ||keys||^2 ----
    if (t < 104) { hs[0][t] = 0.f; hs[1][t] = 0.f; hs[2][t] = 0.f; }
    __syncthreads();
    float hold[3];
    hold[0] = act ? __ldg(&keys[mm[0] * Dd + t]) : 0.f;
    hold[1] = act ? __ldg(&keys[mm[1] * Dd + t]) : 0.f;
    hold[2] = (act && three) ? __ldg(&keys[mm[2] * Dd + t]) : 0.f;
    if (act) { hs[0][t] = hold[0]; hs[1][t] = hold[1]; hs[2][t] = hold[2]; }
    {
        float q0 = hold[0] * hold[0], q1 = hold[1] * hold[1], q2 = hold[2] * hold[2];
#pragma unroll
        for (int o = 16; o > 0; o >>= 1) {
            q0 += __shfl_down_sync(0xffffffffu, q0, o);
            q1 += __shfl_down_sync(0xffffffffu, q1, o);
            q2 += __shfl_down_sync(0xffffffffu, q2, o);
        }
        if (lane == 0) {
            redA[0][w] = q0;
            redA[1][w] = q1;
            redA[2][w] = q2;
        }
    }
    __syncthreads();
    float hh[3];
#pragma unroll
    for (int j = 0; j < 3; ++j)
        hh[j] = redA[j][0] + redA[j][1] + redA[j][2] + redA[j][3];

    // per-slot stream offsets (int: max ~820K elements)
    int eswOff[3], kgOff[3];
#pragma unroll
    for (int j = 0; j < 3; ++j) {
        eswOff[j] = bb[j] * Ss * Dd + t;          // float2 elements
        kgOff[j]  = bb[j] * Ss * Mm + mm[j];
    }

    float2 esw[3];
    float kgv[3];
    esw[0] = act ? g_esw[eswOff[0]] : make_float2(0.f, 0.f);
    esw[1] = act ? g_esw[eswOff[1]] : make_float2(0.f, 0.f);
    esw[2] = (act && three) ? g_esw[eswOff[2]] : make_float2(0.f, 0.f);
    kgv[0] = __ldg(&g_kg[kgOff[0]]);
    kgv[1] = __ldg(&g_kg[kgOff[1]]);
    kgv[2] = three ? __ldg(&g_kg[kgOff[2]]) : 0.f;
    __syncthreads();

    const ULL* hu0 = (const ULL*)hs[0];
    const ULL* hu1 = (const ULL*)hs[1];
    const ULL* hu2 = (const ULL*)hs[2];

    for (int s = 0; s < Ss; ++s) {
        // ======== phase 1: matvec partials + wp chains (independent) ========
        ULL a0[4] = {0, 0, 0, 0}, a1[4] = {0, 0, 0, 0}, a2[4] = {0, 0, 0, 0};
        int hb = 13 * w;
        if (three) {
#pragma unroll
            for (int k = 0; k < 13; ++k) {
                ULL x0 = hu0[hb + k], x1 = hu1[hb + k], x2 = hu2[hb + k];
                fma2(a0[0], x0, U2[0][k]);
                fma2(a1[0], x1, U2[0][k]);
                fma2(a2[0], x2, U2[0][k]);
                fma2(a0[1], x0, U2[1][k]);
                fma2(a1[1], x1, U2[1][k]);
                fma2(a2[1], x2, U2[1][k]);
                fma2(a0[2], x0, U2[2][k]);
                fma2(a1[2], x1, U2[2][k]);
                fma2(a2[2], x2, U2[2][k]);
                fma2(a0[3], x0, U2[3][k]);
                fma2(a1[3], x1, U2[3][k]);
                fma2(a2[3], x2, U2[3][k]);
            }
        } else {
#pragma unroll
            for (int k = 0; k < 13; ++k) {
                ULL x0 = hu0[hb + k], x1 = hu1[hb + k];
                fma2(a0[0], x0, U2[0][k]);
                fma2(a1[0], x1, U2[0][k]);
                fma2(a0[1], x0, U2[1][k]);
                fma2(a1[1], x1, U2[1][k]);
                fma2(a0[2], x0, U2[2][k]);
                fma2(a1[2], x1, U2[2][k]);
                fma2(a0[3], x0, U2[3][k]);
                fma2(a1[3], x1, U2[3][k]);
            }
        }
        // wp chains (no dependence on matvec results -> overlaps FMA latency)
        {
            float wp0 = hold[0] * esw[0].x;
            float wp1 = hold[1] * esw[1].x;
            float wp2 = hold[2] * esw[2].x;
            if (three) {
#pragma unroll
                for (int o = 16; o > 0; o >>= 1) {
                    wp0 += __shfl_down_sync(0xffffffffu, wp0, o);
                    wp1 += __shfl_down_sync(0xffffffffu, wp1, o);
                    wp2 += __shfl_down_sync(0xffffffffu, wp2, o);
                }
            } else {
#pragma unroll
                for (int o = 16; o > 0; o >>= 1) {
                    wp0 += __shfl_down_sync(0xffffffffu, wp0, o);
                    wp1 += __shfl_down_sync(0xffffffffu, wp1, o);
                }
            }
            if (lane == 0) {
                redA[0][w] = wp0;
                redA[1][w] = wp1;
                redA[2][w] = wp2;
            }
        }
#pragma unroll
        for (int j = 0; j < 4; ++j) {
            int e = lane + 32 * j;
            part[0][w][e] = sum2(a0[j]);
            part[1][w][e] = sum2(a1[j]);
            if (three) part[2][w][e] = sum2(a2[j]);
        }
        __syncthreads();   // bar A

        // ======== phase 2: candidates + hc/cc chains ========
        float c[3];
        {
            float pz = (part[0][0][t] + part[0][1][t]) + (part[0][2][t] + part[0][3][t]);
            float v = kv[0] + esw[0].y + pz;
            c[0] = (v >= 0.f) ? v : aprelu * v;
            pz = (part[1][0][t] + part[1][1][t]) + (part[1][2][t] + part[1][3][t]);
            v = kv[1] + esw[1].y + pz;
            c[1] = (v >= 0.f) ? v : aprelu * v;
            c[2] = 0.f;
            if (three) {
                pz = (part[2][0][t] + part[2][1][t]) + (part[2][2][t] + part[2][3][t]);
                v = kv[2] + esw[2].y + pz;
                c[2] = (v >= 0.f) ? v : aprelu * v;
            }
        }
        {
            float h0p = hold[0] * c[0], q0 = c[0] * c[0];
            float h1p = hold[1] * c[1], q1 = c[1] * c[1];
            float h2p = hold[2] * c[2], q2 = c[2] * c[2];
            if (three) {
#pragma unroll
                for (int o = 16; o > 0; o >>= 1) {
                    h0p += __shfl_down_sync(0xffffffffu, h0p, o);
                    h1p += __shfl_down_sync(0xffffffffu, h1p, o);
                    h2p += __shfl_down_sync(0xffffffffu, h2p, o);
                    q0  += __shfl_down_sync(0xffffffffu, q0, o);
                    q1  += __shfl_down_sync(0xffffffffu, q1, o);
                    q2  += __shfl_down_sync(0xffffffffu, q2, o);
                }
            } else {
#pragma unroll
                for (int o = 16; o > 0; o >>= 1) {
                    h0p += __shfl_down_sync(0xffffffffu, h0p, o);
                    h1p += __shfl_down_sync(0xffffffffu, h1p, o);
                    q0  += __shfl_down_sync(0xffffffffu, q0, o);
                    q1  += __shfl_down_sync(0xffffffffu, q1, o);
                }
            }
            if (lane == 0) {
                redB[0][w] = make_float2(h0p, q0);
                redB[1][w] = make_float2(h1p, q1);
                redB[2][w] = make_float2(h2p, q2);
            }
        }

        // ---- prefetch next step ----
        float2 eswn[3];
        float kgn[3];
#pragma unroll
        for (int j = 0; j < 3; ++j) { eswn[j] = esw[j]; kgn[j] = kgv[j]; }
        if (s + 1 < Ss) {
            int so = (s + 1) * Dd;
            eswn[0] = act ? g_esw[eswOff[0] + so] : make_float2(0.f, 0.f);
            eswn[1] = act ? g_esw[eswOff[1] + so] : make_float2(0.f, 0.f);
            kgn[0] = __ldg(&g_kg[kgOff[0] + (s + 1) * Mm]);
            kgn[1] = __ldg(&g_kg[kgOff[1] + (s + 1) * Mm]);
            if (three) {
                eswn[2] = act ? g_esw[eswOff[2] + so] : make_float2(0.f, 0.f);
                kgn[2] = __ldg(&g_kg[kgOff[2] + (s + 1) * Mm]);
            }
        }
        __syncthreads();   // bar B

        // ======== phase 3: gate, norm, update, store ========
#pragma unroll
        for (int j = 0; j < 3; ++j) {
            if (j == 2 && !three) break;
            float swp = redA[j][0] + redA[j][1] + redA[j][2] + redA[j][3];
            float2 r0 = redB[j][0], r1 = redB[j][1], r2 = redB[j][2], r3 = redB[j][3];
            float shc = (r0.x + r1.x) + (r2.x + r3.x);
            float scc = (r0.y + r1.y) + (r2.y + r3.y);
            float g = 1.f / (1.f + __expf(-(swp + kgv[j])));
            float nn = hh[j] + 2.f * g * shc + g * g * scc;
            float rr = rsqrtf(nn);
            float hn = (hold[j] + c[j] * g) * rr;
            if (!act) hn = 0.f;
            if (act) hs[j][t] = hn;
            hold[j] = hn;
            hh[j] = 1.f;
        }
        __syncthreads();   // bar C

#pragma unroll
        for (int j = 0; j < 3; ++j) { esw[j] = eswn[j]; kgv[j] = kgn[j]; }
    }

    if (act) {
        out[(size_t)sl[0] * Dd + t] = hold[0];
        out[(size_t)sl[1] * Dd + t] = hold[1];
        if (three) out[(size_t)sl[2] * Dd + t] = hold[2];
    }
}

// ================= launcher =================
extern "C" void kernel_launch(void* const* d_in, const int* in_sizes, int n_in,
                              void* d_out, int out_size) {
    const float* batch = (const float*)d_in[0];  // [B,S,L,D]
    const float* mult  = (const float*)d_in[1];  // [L,D]
    const float* keys  = (const float*)d_in[2];  // [M,D]
    const float* U     = (const float*)d_in[3];  // [D,D]
    const float* V     = (const float*)d_in[4];  // [D,D]
    const float* W     = (const float*)d_in[5];  // [D,D]
    const float* pa    = (const float*)d_in[6];  // scalar
    float* out = (float*)d_out;                  // [B,M,D]

    float4* enc4;
    cudaGetSymbolAddress((void**)&enc4, g_enc);

    k_encode<<<Bb * Ss, 128>>>((const float4*)batch, (const float4*)mult, enc4);
    k_project<<<(Bb * Ss) / R2, 128>>>(W, keys);
    k_scan<<<NBLK, 128>>>(keys, U, V, pa, out);
}

// round 11
// speedup vs baseline: 1.0328x; 1.0328x over previous
#include <cuda_runtime.h>
#include <cstdint>

#define Bb 32
#define Ss 256
#define Ll 64
#define Dd 100
#define Mm 20
#define NSLOT (Bb * Mm)   // 640
#define NBLK (NSLOT / 2)  // 320 blocks, 2 slots each (same batch)

typedef unsigned long long ULL;

// ---------------- scratch (no allocations allowed) ----------------
__device__ __align__(16) float  g_enc [Bb * Ss * Dd];      // [B,S,D]
__device__ __align__(16) float2 g_esw [Bb * Ss * Dd];      // [B,S,D] (enc, enc@W^T)
__device__ __align__(16) float  g_kg  [Bb * Ss * Mm];      // [B,S,M] enc . keys[m]

// ---------------- helpers ----------------
__device__ __forceinline__ void fma2(ULL& acc, ULL a, ULL b) {
    asm("fma.rn.f32x2 %0, %1, %2, %0;" : "+l"(acc) : "l"(a), "l"(b));
}
__device__ __forceinline__ ULL pack2(float lo, float hi) {
    ULL r;
    asm("mov.b64 %0, {%1, %2};" : "=l"(r) : "f"(lo), "f"(hi));
    return r;
}
__device__ __forceinline__ float sum2(ULL v) {
    float lo, hi;
    asm("mov.b64 {%0, %1}, %2;" : "=f"(lo), "=f"(hi) : "l"(v));
    return lo + hi;
}

// ================= K1: encode (float4 path) =================
__global__ void k_encode(const float4* __restrict__ batch4,
                         const float4* __restrict__ mult4,
                         float4* __restrict__ enc4) {
    __shared__ float4 sm4[100];
    int row = blockIdx.x;           // b*S + s
    int t = threadIdx.x;

    if (t < 100) {
        int c  = t % 25;
        int lg = t / 25;
        const float4* bp = batch4 + (size_t)row * (Ll * 25);
        float4 acc = make_float4(0.f, 0.f, 0.f, 0.f);
#pragma unroll
        for (int k = 0; k < 16; ++k) {
            int l = lg + 4 * k;
            float4 bv = bp[l * 25 + c];
            float4 mv = __ldg(&mult4[l * 25 + c]);
            acc.x += bv.x * mv.x;
            acc.y += bv.y * mv.y;
            acc.z += bv.z * mv.z;
            acc.w += bv.w * mv.w;
        }
        sm4[t] = acc;
    }
    __syncthreads();
    if (t < 25) {
        float4 a = sm4[t], b = sm4[t + 25], c = sm4[t + 50], d = sm4[t + 75];
        float4 r;
        r.x = (a.x + b.x) + (c.x + d.x);
        r.y = (a.y + b.y) + (c.y + d.y);
        r.z = (a.z + b.z) + (c.z + d.z);
        r.w = (a.w + b.w) + (c.w + d.w);
        enc4[(size_t)row * 25 + t] = r;
    }
}

// ================= K2: project -> g_esw=(enc, enc@W^T), g_kg =================
#define R2 16
__global__ void k_project(const float* __restrict__ W,
                          const float* __restrict__ keys) {
    __shared__ float Wt[Dd * Dd];        // Wt[d*Dd + e] = W[e*Dd + d]
    __shared__ float encs[R2][Dd];
    int t = threadIdx.x;
    int row0 = blockIdx.x * R2;

    for (int idx = t; idx < Dd * Dd; idx += blockDim.x) {
        int e = idx / Dd, d = idx % Dd;
        Wt[d * Dd + e] = W[idx];
    }
    for (int idx = t; idx < R2 * Dd; idx += blockDim.x)
        ((float*)encs)[idx] = g_enc[(size_t)row0 * Dd + idx];
    __syncthreads();

    if (t < Dd) {
        for (int r = 0; r < R2; ++r) {
            float acc = 0.f;
#pragma unroll 4
            for (int d = 0; d < Dd; ++d)
                acc += encs[r][d] * Wt[d * Dd + t];
            g_esw[(size_t)(row0 + r) * Dd + t] = make_float2(encs[r][t], acc);
        }
    } else if (t < Dd + Mm) {
        int m = t - Dd;
        for (int r = 0; r < R2; ++r) {
            float acc = 0.f;
#pragma unroll 4
            for (int d = 0; d < Dd; ++d)
                acc += encs[r][d] * __ldg(&keys[m * Dd + d]);
            g_kg[(size_t)(row0 + r) * Mm + m] = acc;
        }
    }
}

// ================= K3: scan — ONE __syncthreads per step =================
// State: warp w owns dims [25w, 25w+25), lane l<25 owns e_st = 25w+l.
// h kept UN-normalized (u) in warp-private smem (us) — only warp w touches
// its region, so h-update -> matvec needs only __syncwarp.
// Norm scalar r_s = rsqrt(hh + 2 g_{s-1} shc + g_{s-1}^2 scc) from the
// PREVIOUS step's hc/cc partials (read after this step's single barrier).
// Matvec output: lane computes rows e = lane+32j (j<4) over warp's d-range.
// Cross-warp traffic (part, wp, hc/cc) double-buffered.
__global__ void __launch_bounds__(128, 3)
k_scan(const float* __restrict__ keys, const float* __restrict__ U,
       const float* __restrict__ V, const float* __restrict__ prelu_a,
       float* __restrict__ out) {
    __shared__ __align__(16) float us[2][4][28];     // [slot][warp][dim] pad 25..27 = 0
    __shared__ float part[2][2][4][128];             // [buf][slot][warp][e_out]
    __shared__ float wpS[2][2][4];                   // [buf][slot][warp]
    __shared__ float2 hcS[2][2][4];                  // [buf][slot][warp] = (hc, cc)
    __shared__ float redI[2][4];

    int bid = blockIdx.x;
    int sl0 = 2 * bid, sl1 = sl0 + 1;
    int b  = sl0 / Mm;
    int m0 = sl0 % Mm, m1 = m0 + 1;                  // same batch (Mm even)

    int t = threadIdx.x;
    int lane = t & 31, w = t >> 5;
    int e_st = 25 * w + lane;                        // state dim (lane<25)
    bool act = (lane < 25);
    float aprelu = __ldg(prelu_a);

    // ---- U tile for matvec outputs: rows e=lane+32j, cols = warp's d-range ----
    // pair k covers d = 25w+2k, 25w+2k+1 (second element 0 when 2k+1==25:
    // that d belongs to the next warp's range; u pad[25]=0 keeps it consistent)
    ULL U2[4][13];
#pragma unroll
    for (int j = 0; j < 4; ++j) {
        int e = lane + 32 * j;
#pragma unroll
        for (int k = 0; k < 13; ++k) {
            int d = 25 * w + 2 * k;
            float u0 = (e < Dd && d < 25 * w + 25) ? __ldg(&U[e * Dd + d]) : 0.f;
            float u1 = (e < Dd && d + 1 < 25 * w + 25) ? __ldg(&U[e * Dd + d + 1]) : 0.f;
            U2[j][k] = pack2(u0, u1);
        }
    }

    // ---- step-invariant keysV[m, e_st] ----
    float kv0 = 0.f, kv1 = 0.f;
    if (act) {
#pragma unroll 4
        for (int d = 0; d < Dd; ++d) {
            float ve = __ldg(&V[e_st * Dd + d]);
            kv0 += __ldg(&keys[m0 * Dd + d]) * ve;
            kv1 += __ldg(&keys[m1 * Dd + d]) * ve;
        }
    }

    // ---- init: u0 = raw keys; hh = ||keys||^2; zero pads & buffers ----
    float hold0 = act ? __ldg(&keys[m0 * Dd + e_st]) : 0.f;
    float hold1 = act ? __ldg(&keys[m1 * Dd + e_st]) : 0.f;
    if (lane < 28) {
        us[0][w][lane] = act ? hold0 : 0.f;
        us[1][w][lane] = act ? hold1 : 0.f;
    }
    if (lane < 2) {
        hcS[1][lane][w] = make_float2(0.f, 0.f);     // read at s=0 (g_prev=0)
    }
    {
        float q0 = hold0 * hold0, q1 = hold1 * hold1;
#pragma unroll
        for (int o = 16; o > 0; o >>= 1) {
            q0 += __shfl_down_sync(0xffffffffu, q0, o);
            q1 += __shfl_down_sync(0xffffffffu, q1, o);
        }
        if (lane == 0) { redI[0][w] = q0; redI[1][w] = q1; }
    }
    __syncthreads();
    float hh0 = redI[0][0] + redI[0][1] + redI[0][2] + redI[0][3];
    float hh1 = redI[1][0] + redI[1][1] + redI[1][2] + redI[1][3];

    const float2* eswp = g_esw + (size_t)b * Ss * Dd;
    const float2* kgp  = (const float2*)(g_kg + (size_t)b * Ss * Mm + m0);

    float2 esw = act ? eswp[e_st] : make_float2(0.f, 0.f);
    float2 kg  = __ldg(&kgp[0]);
    float g0p = 0.f, g1p = 0.f;          // gate of previous step

    const ULL* u0p = (const ULL*)us[0][w];
    const ULL* u1p = (const ULL*)us[1][w];

    for (int s = 0; s < Ss; ++s) {
        int bb = s & 1;

        // ======== pre-bar: matvec on u (own warp region) + wp chains ========
        ULL a0[4] = {0, 0, 0, 0}, a1[4] = {0, 0, 0, 0};
#pragma unroll
        for (int k = 0; k < 13; ++k) {
            ULL x0 = u0p[k];
            ULL x1 = u1p[k];
            fma2(a0[0], x0, U2[0][k]);
            fma2(a1[0], x1, U2[0][k]);
            fma2(a0[1], x0, U2[1][k]);
            fma2(a1[1], x1, U2[1][k]);
            fma2(a0[2], x0, U2[2][k]);
            fma2(a1[2], x1, U2[2][k]);
            fma2(a0[3], x0, U2[3][k]);
            fma2(a1[3], x1, U2[3][k]);
        }
        // wp partial chains on UN-normalized u (scaled by r after bar)
        {
            float wp0 = hold0 * esw.x;
            float wp1 = hold1 * esw.x;
#pragma unroll
            for (int o = 16; o > 0; o >>= 1) {
                wp0 += __shfl_down_sync(0xffffffffu, wp0, o);
                wp1 += __shfl_down_sync(0xffffffffu, wp1, o);
            }
            if (lane == 0) {
                wpS[bb][0][w] = wp0;
                wpS[bb][1][w] = wp1;
            }
        }
#pragma unroll
        for (int j = 0; j < 4; ++j) {
            int e = lane + 32 * j;
            part[bb][0][w][e] = sum2(a0[j]);
            part[bb][1][w][e] = sum2(a1[j]);
        }
        __syncthreads();    // THE barrier

        // ======== post-bar ========
        // previous step's hc/cc -> r for u_s
        float2 pA0 = hcS[bb ^ 1][0][0], pA1 = hcS[bb ^ 1][0][1],
               pA2 = hcS[bb ^ 1][0][2], pA3 = hcS[bb ^ 1][0][3];
        float2 pB0 = hcS[bb ^ 1][1][0], pB1 = hcS[bb ^ 1][1][1],
               pB2 = hcS[bb ^ 1][1][2], pB3 = hcS[bb ^ 1][1][3];
        float shc0 = (pA0.x + pA1.x) + (pA2.x + pA3.x);
        float scc0 = (pA0.y + pA1.y) + (pA2.y + pA3.y);
        float shc1 = (pB0.x + pB1.x) + (pB2.x + pB3.x);
        float scc1 = (pB0.y + pB1.y) + (pB2.y + pB3.y);

        float swu0 = wpS[bb][0][0] + wpS[bb][0][1] + wpS[bb][0][2] + wpS[bb][0][3];
        float swu1 = wpS[bb][1][0] + wpS[bb][1][1] + wpS[bb][1][2] + wpS[bb][1][3];

        float q0 = (part[bb][0][0][e_st] + part[bb][0][1][e_st])
                 + (part[bb][0][2][e_st] + part[bb][0][3][e_st]);
        float q1 = (part[bb][1][0][e_st] + part[bb][1][1][e_st])
                 + (part[bb][1][2][e_st] + part[bb][1][3][e_st]);

        float n0 = hh0 + 2.f * g0p * shc0 + g0p * g0p * scc0;
        float n1 = hh1 + 2.f * g1p * shc1 + g1p * g1p * scc1;
        float rr0 = (s == 0) ? 1.f : rsqrtf(n0);
        float rr1 = (s == 0) ? 1.f : rsqrtf(n1);

        // candidates (true mem = rr * u)
        float c0 = 0.f, c1 = 0.f;
        if (act) {
            float v0 = kv0 + esw.y + rr0 * q0;
            float v1 = kv1 + esw.y + rr1 * q1;
            c0 = (v0 >= 0.f) ? v0 : aprelu * v0;
            c1 = (v1 >= 0.f) ? v1 : aprelu * v1;
        }

        float g0 = 1.f / (1.f + __expf(-(rr0 * swu0 + kg.x)));
        float g1 = 1.f / (1.f + __expf(-(rr1 * swu1 + kg.y)));

        float hn0 = rr0 * hold0 + c0 * g0;   // u_{s+1} (un-normalized)
        float hn1 = rr1 * hold1 + c1 * g1;
        if (act) {
            us[0][w][lane] = hn0;            // warp-private: syncwarp suffices
            us[1][w][lane] = hn1;
        }

        // hc/cc chains on (normalized hold, c) for NEXT step's r
        {
            float hb0 = rr0 * hold0;
            float hb1 = rr1 * hold1;
            float hc0 = hb0 * c0, cc0 = c0 * c0;
            float hc1 = hb1 * c1, cc1 = c1 * c1;
#pragma unroll
            for (int o = 16; o > 0; o >>= 1) {
                hc0 += __shfl_down_sync(0xffffffffu, hc0, o);
                hc1 += __shfl_down_sync(0xffffffffu, hc1, o);
                cc0 += __shfl_down_sync(0xffffffffu, cc0, o);
                cc1 += __shfl_down_sync(0xffffffffu, cc1, o);
            }
            if (lane == 0) {
                hcS[bb][0][w] = make_float2(hc0, cc0);
                hcS[bb][1][w] = make_float2(hc1, cc1);
            }
        }

        // prefetch next step's streams
        if (s + 1 < Ss) {
            esw = act ? eswp[(size_t)(s + 1) * Dd + e_st] : make_float2(0.f, 0.f);
            kg  = __ldg(&kgp[(size_t)(s + 1) * (Mm / 2)]);
        }

        hold0 = hn0;
        hold1 = hn1;
        g0p = g0;
        g1p = g1;
        if (s > 0) { hh0 = 1.f; hh1 = 1.f; }   // normalized from step>=1 on
        __syncwarp();    // own-warp u writes visible for next matvec
    }

    // ---- final normalize of u_Ss using last step's hc/cc ----
    __syncthreads();
    {
        int bb = (Ss - 1) & 1;
        float2 pA0 = hcS[bb][0][0], pA1 = hcS[bb][0][1],
               pA2 = hcS[bb][0][2], pA3 = hcS[bb][0][3];
        float2 pB0 = hcS[bb][1][0], pB1 = hcS[bb][1][1],
               pB2 = hcS[bb][1][2], pB3 = hcS[bb][1][3];
        float shc0 = (pA0.x + pA1.x) + (pA2.x + pA3.x);
        float scc0 = (pA0.y + pA1.y) + (pA2.y + pA3.y);
        float shc1 = (pB0.x + pB1.x) + (pB2.x + pB3.x);
        float scc1 = (pB0.y + pB1.y) + (pB2.y + pB3.y);
        float n0 = hh0 + 2.f * g0p * shc0 + g0p * g0p * scc0;
        float n1 = hh1 + 2.f * g1p * shc1 + g1p * g1p * scc1;
        float rr0 = rsqrtf(n0);
        float rr1 = rsqrtf(n1);
        if (act) {
            out[(size_t)sl0 * Dd + e_st] = rr0 * hold0;
            out[(size_t)sl1 * Dd + e_st] = rr1 * hold1;
        }
    }
}

// ================= launcher =================
extern "C" void kernel_launch(void* const* d_in, const int* in_sizes, int n_in,
                              void* d_out, int out_size) {
    const float* batch = (const float*)d_in[0];  // [B,S,L,D]
    const float* mult  = (const float*)d_in[1];  // [L,D]
    const float* keys  = (const float*)d_in[2];  // [M,D]
    const float* U     = (const float*)d_in[3];  // [D,D]
    const float* V     = (const float*)d_in[4];  // [D,D]
    const float* W     = (const float*)d_in[5];  // [D,D]
    const float* pa    = (const float*)d_in[6];  // scalar
    float* out = (float*)d_out;                  // [B,M,D]

    float4* enc4;
    cudaGetSymbolAddress((void**)&enc4, g_enc);

    k_encode<<<Bb * Ss, 128>>>((const float4*)batch, (const float4*)mult, enc4);
    k_project<<<(Bb * Ss) / R2, 128>>>(W, keys);
    k_scan<<<NBLK, 128>>>(keys, U, V, pa, out);
}

// round 12
// speedup vs baseline: 1.2536x; 1.2138x over previous
#include <cuda_runtime.h>
#include <cstdint>

#define Bb 32
#define Ss 256
#define Ll 64
#define Dd 100
#define Mm 20
#define NSLOT (Bb * Mm)   // 640
#define NBLK (NSLOT / 2)  // 320 blocks, 2 slots each (same batch)

typedef unsigned long long ULL;

// ---------------- scratch (no allocations allowed) ----------------
__device__ __align__(16) float  g_enc [Bb * Ss * Dd];      // [B,S,D]
__device__ __align__(16) float2 g_esw [Bb * Ss * Dd];      // [B,S,D] (enc, enc@W^T)
__device__ __align__(16) float  g_kg  [Bb * Ss * Mm];      // [B,S,M] enc . keys[m]

// ---------------- helpers ----------------
__device__ __forceinline__ void fma2(ULL& acc, ULL a, ULL b) {
    asm("fma.rn.f32x2 %0, %1, %2, %0;" : "+l"(acc) : "l"(a), "l"(b));
}
__device__ __forceinline__ ULL pack2(float lo, float hi) {
    ULL r;
    asm("mov.b64 %0, {%1, %2};" : "=l"(r) : "f"(lo), "f"(hi));
    return r;
}
__device__ __forceinline__ float sum2(ULL v) {
    float lo, hi;
    asm("mov.b64 {%0, %1}, %2;" : "=f"(lo), "=f"(hi) : "l"(v));
    return lo + hi;
}
__device__ __forceinline__ void unpack2(ULL v, float& lo, float& hi) {
    asm("mov.b64 {%0, %1}, %2;" : "=f"(lo), "=f"(hi) : "l"(v));
}

// ================= K1: encode (float4 path) =================
__global__ void k_encode(const float4* __restrict__ batch4,
                         const float4* __restrict__ mult4,
                         float4* __restrict__ enc4) {
    __shared__ float4 sm4[100];
    int row = blockIdx.x;           // b*S + s
    int t = threadIdx.x;

    if (t < 100) {
        int c  = t % 25;
        int lg = t / 25;
        const float4* bp = batch4 + (size_t)row * (Ll * 25);
        float4 acc = make_float4(0.f, 0.f, 0.f, 0.f);
#pragma unroll
        for (int k = 0; k < 16; ++k) {
            int l = lg + 4 * k;
            float4 bv = bp[l * 25 + c];
            float4 mv = __ldg(&mult4[l * 25 + c]);
            acc.x += bv.x * mv.x;
            acc.y += bv.y * mv.y;
            acc.z += bv.z * mv.z;
            acc.w += bv.w * mv.w;
        }
        sm4[t] = acc;
    }
    __syncthreads();
    if (t < 25) {
        float4 a = sm4[t], b = sm4[t + 25], c = sm4[t + 50], d = sm4[t + 75];
        float4 r;
        r.x = (a.x + b.x) + (c.x + d.x);
        r.y = (a.y + b.y) + (c.y + d.y);
        r.z = (a.z + b.z) + (c.z + d.z);
        r.w = (a.w + b.w) + (c.w + d.w);
        enc4[(size_t)row * 25 + t] = r;
    }
}

// ================= K2: project (tiled GEMM) =================
// Out[8192,120] = enc[8192,100] @ Z[100,120], Z = [W^T | keys^T].
// Grid 128 x 64-row tiles. Thread (ry,ex): rows ry*4..+3, cols {4ex+32g+k}.
// d-chunked Z in smem (25 rows/chunk). All smem access conflict-free:
//   Z frag: 8 x 16B segments = all 32 banks; enc pitch 106 -> 8-bank spread.
#define PRT 64
#define DCH 25
#define EPITCH 106
__global__ void __launch_bounds__(128, 1)
k_project(const float* __restrict__ W, const float* __restrict__ keys) {
    __shared__ __align__(16) float encs[PRT * EPITCH];   // 27.1 KB
    __shared__ __align__(16) float Z[DCH * 128];         // 12.8 KB
    int t = threadIdx.x;
    int ex = t & 7, ry = t >> 3;          // ex<8, ry<16
    int row0 = blockIdx.x * PRT;

    // load enc tile
    for (int i = t; i < PRT * Dd; i += 128) {
        int r = i / Dd, c = i % Dd;
        encs[r * EPITCH + c] = g_enc[(size_t)(row0 + r) * Dd + c];
    }

    ULL acc[4][8];
#pragma unroll
    for (int i = 0; i < 4; ++i)
#pragma unroll
        for (int g = 0; g < 8; ++g) acc[i][g] = 0ull;

    for (int d0 = 0; d0 < Dd; d0 += DCH) {
        __syncthreads();
        for (int i = t; i < DCH * 128; i += 128) {
            int dd = i >> 7, n = i & 127;
            int d = d0 + dd;
            float v = 0.f;
            if (n < 100)      v = __ldg(&W[n * Dd + d]);
            else if (n < 120) v = __ldg(&keys[(n - 100) * Dd + d]);
            Z[dd * 128 + n] = v;
        }
        __syncthreads();
#pragma unroll 5
        for (int dd = 0; dd < DCH; ++dd) {
            ULL z2[8];
#pragma unroll
            for (int g = 0; g < 4; ++g) {
                float4 zv = *(const float4*)&Z[dd * 128 + 4 * ex + 32 * g];
                z2[2 * g]     = pack2(zv.x, zv.y);
                z2[2 * g + 1] = pack2(zv.z, zv.w);
            }
#pragma unroll
            for (int i = 0; i < 4; ++i) {
                float rv = encs[(ry * 4 + i) * EPITCH + d0 + dd];
                ULL r2 = pack2(rv, rv);
#pragma unroll
                for (int g = 0; g < 8; ++g) fma2(acc[i][g], r2, z2[g]);
            }
        }
    }
    __syncthreads();

    // store: cols cj = 4*ex + 32*g + k
#pragma unroll
    for (int i = 0; i < 4; ++i) {
        int rl = ry * 4 + i;
        int row = row0 + rl;
#pragma unroll
        for (int g = 0; g < 4; ++g) {
            float v0, v1, v2, v3;
            unpack2(acc[i][2 * g], v0, v1);
            unpack2(acc[i][2 * g + 1], v2, v3);
            float vv[4] = {v0, v1, v2, v3};
#pragma unroll
            for (int k = 0; k < 4; ++k) {
                int cj = 4 * ex + 32 * g + k;
                if (cj < 100) {
                    g_esw[(size_t)row * Dd + cj] =
                        make_float2(encs[rl * EPITCH + cj], vv[k]);
                } else if (cj < 120) {
                    g_kg[(size_t)row * Mm + (cj - 100)] = vv[k];
                }
            }
        }
    }
}

// ================= K3: scan (R8-exact), 128 threads, warp-d-split =================
__global__ void __launch_bounds__(128, 3)
k_scan(const float* __restrict__ keys, const float* __restrict__ U,
       const float* __restrict__ V, const float* __restrict__ prelu_a,
       float* __restrict__ out) {
    __shared__ __align__(16) float h0s[104];     // pads [100,104) = 0
    __shared__ __align__(16) float h1s[104];
    __shared__ float part[2][4][128];            // [slot][dwarp][e]
    __shared__ float4 redA[4];                   // (wp0, wp1, hc0, hc1)
    __shared__ float2 redB[4];                   // (cc0, cc1)

    int bid = blockIdx.x;
    int sl0 = 2 * bid, sl1 = sl0 + 1;
    int b  = sl0 / Mm;
    int m0 = sl0 % Mm, m1 = m0 + 1;              // m0 even -> same batch

    int t = threadIdx.x;
    int lane = t & 31, w = t >> 5;
    bool act = (t < Dd);
    float aprelu = __ldg(prelu_a);

    // ---- U quarter-tile: 4 e-rows x 13 d-pairs (my warp's d-range) ----
    ULL U2[4][13];
#pragma unroll
    for (int j = 0; j < 4; ++j) {
        int e = lane + 32 * j;
#pragma unroll
        for (int k = 0; k < 13; ++k) {
            int d = 26 * w + 2 * k;
            float u0 = (e < Dd && d     < Dd) ? __ldg(&U[e * Dd + d])     : 0.f;
            float u1 = (e < Dd && d + 1 < Dd) ? __ldg(&U[e * Dd + d + 1]) : 0.f;
            U2[j][k] = pack2(u0, u1);
        }
    }

    // ---- step-invariant keysV[m,e] on state mapping ----
    float kv0 = 0.f, kv1 = 0.f;
    if (act) {
#pragma unroll 4
        for (int d = 0; d < Dd; ++d) {
            float ve = __ldg(&V[t * Dd + d]);
            kv0 += __ldg(&keys[m0 * Dd + d]) * ve;
            kv1 += __ldg(&keys[m1 * Dd + d]) * ve;
        }
    }

    // ---- init: h = raw keys; hh = ||keys||^2 ----
    if (t < 104) { h0s[t] = 0.f; h1s[t] = 0.f; }
    __syncthreads();
    float hold0 = act ? __ldg(&keys[m0 * Dd + t]) : 0.f;
    float hold1 = act ? __ldg(&keys[m1 * Dd + t]) : 0.f;
    if (act) { h0s[t] = hold0; h1s[t] = hold1; }
    {
        float q0 = hold0 * hold0, q1 = hold1 * hold1;
#pragma unroll
        for (int o = 16; o > 0; o >>= 1) {
            q0 += __shfl_down_sync(0xffffffffu, q0, o);
            q1 += __shfl_down_sync(0xffffffffu, q1, o);
        }
        if (lane == 0) redB[w] = make_float2(q0, q1);
    }
    __syncthreads();
    float hh0 = redB[0].x + redB[1].x + redB[2].x + redB[3].x;
    float hh1 = redB[0].y + redB[1].y + redB[2].y + redB[3].y;

    const float2* eswp = g_esw + (size_t)b * Ss * Dd;
    const float2* kgp  = (const float2*)(g_kg + (size_t)b * Ss * Mm + m0);

    float2 esw = act ? eswp[t] : make_float2(0.f, 0.f);
    float2 kg  = __ldg(&kgp[0]);
    __syncthreads();

    const ULL* h0u = (const ULL*)h0s;
    const ULL* h1u = (const ULL*)h1s;

    for (int s = 0; s < Ss; ++s) {
        // ---- matvec partials: my warp's 26-dim d-range, 4 e's, 2 slots ----
        ULL a0[4] = {0, 0, 0, 0};
        ULL a1[4] = {0, 0, 0, 0};
        int hb = 13 * w;
#pragma unroll
        for (int k = 0; k < 13; ++k) {
            ULL x = h0u[hb + k];
            ULL y = h1u[hb + k];
            fma2(a0[0], x, U2[0][k]);
            fma2(a1[0], y, U2[0][k]);
            fma2(a0[1], x, U2[1][k]);
            fma2(a1[1], y, U2[1][k]);
            fma2(a0[2], x, U2[2][k]);
            fma2(a1[2], y, U2[2][k]);
            fma2(a0[3], x, U2[3][k]);
            fma2(a1[3], y, U2[3][k]);
        }
#pragma unroll
        for (int j = 0; j < 4; ++j) {
            int e = lane + 32 * j;
            part[0][w][e] = sum2(a0[j]);
            part[1][w][e] = sum2(a1[j]);
        }
        __syncthreads();   // bar A: partials visible; h reads done

        // ---- gather candidates on state mapping ----
        float p0 = (part[0][0][t] + part[0][1][t]) + (part[0][2][t] + part[0][3][t]);
        float p1 = (part[1][0][t] + part[1][1][t]) + (part[1][2][t] + part[1][3][t]);
        float c0 = kv0 + esw.y + p0;
        float c1 = kv1 + esw.y + p1;
        c0 = (c0 >= 0.f) ? c0 : aprelu * c0;
        c1 = (c1 >= 0.f) ? c1 : aprelu * c1;

        // ---- prefetch next step's inputs ----
        float2 eswn = esw, kgn = kg;
        if (s + 1 < Ss) {
            eswn = act ? eswp[(size_t)(s + 1) * Dd + t] : make_float2(0.f, 0.f);
            kgn  = __ldg(&kgp[(size_t)(s + 1) * (Mm / 2)]);
        }

        // ---- merged reductions: wp (hold.enc), hc (hold.c), cc (c.c) ----
        float wp0 = hold0 * esw.x, wp1 = hold1 * esw.x;
        float hc0 = hold0 * c0,    hc1 = hold1 * c1;
        float cc0 = c0 * c0,       cc1 = c1 * c1;
#pragma unroll
        for (int o = 16; o > 0; o >>= 1) {
            wp0 += __shfl_down_sync(0xffffffffu, wp0, o);
            wp1 += __shfl_down_sync(0xffffffffu, wp1, o);
            hc0 += __shfl_down_sync(0xffffffffu, hc0, o);
            hc1 += __shfl_down_sync(0xffffffffu, hc1, o);
            cc0 += __shfl_down_sync(0xffffffffu, cc0, o);
            cc1 += __shfl_down_sync(0xffffffffu, cc1, o);
        }
        if (lane == 0) {
            redA[w] = make_float4(wp0, wp1, hc0, hc1);
            redB[w] = make_float2(cc0, cc1);
        }
        __syncthreads();   // bar B: reductions visible

        float4 A = redA[0], B4 = redA[1], C4 = redA[2], D4 = redA[3];
        float2 E = redB[0], F = redB[1], G2 = redB[2], H2 = redB[3];
        float mg0 = (A.x + B4.x) + (C4.x + D4.x);
        float mg1 = (A.y + B4.y) + (C4.y + D4.y);
        float shc0 = (A.z + B4.z) + (C4.z + D4.z);
        float shc1 = (A.w + B4.w) + (C4.w + D4.w);
        float scc0 = (E.x + F.x) + (G2.x + H2.x);
        float scc1 = (E.y + F.y) + (G2.y + H2.y);

        float g0 = 1.f / (1.f + __expf(-(mg0 + kg.x)));
        float g1 = 1.f / (1.f + __expf(-(mg1 + kg.y)));
        // ||hn||^2 = hh + 2 g (hold.c) + g^2 (c.c)
        float n0 = hh0 + 2.f * g0 * shc0 + g0 * g0 * scc0;
        float n1 = hh1 + 2.f * g1 * shc1 + g1 * g1 * scc1;
        float r0 = rsqrtf(n0);
        float r1 = rsqrtf(n1);

        float hn0 = (hold0 + c0 * g0) * r0;   // normalized
        float hn1 = (hold1 + c1 * g1) * r1;
        if (!act) { hn0 = 0.f; hn1 = 0.f; }
        if (act) { h0s[t] = hn0; h1s[t] = hn1; }
        __syncthreads();   // bar C: h visible for next matvec

        hold0 = hn0;
        hold1 = hn1;
        hh0 = 1.f;
        hh1 = 1.f;
        esw = eswn;
        kg = kgn;
    }

    if (act) {
        out[(size_t)sl0 * Dd + t] = hold0;
        out[(size_t)sl1 * Dd + t] = hold1;
    }
}

// ================= launcher =================
extern "C" void kernel_launch(void* const* d_in, const int* in_sizes, int n_in,
                              void* d_out, int out_size) {
    const float* batch = (const float*)d_in[0];  // [B,S,L,D]
    const float* mult  = (const float*)d_in[1];  // [L,D]
    const float* keys  = (const float*)d_in[2];  // [M,D]
    const float* U     = (const float*)d_in[3];  // [D,D]
    const float* V     = (const float*)d_in[4];  // [D,D]
    const float* W     = (const float*)d_in[5];  // [D,D]
    const float* pa    = (const float*)d_in[6];  // scalar
    float* out = (float*)d_out;                  // [B,M,D]

    float4* enc4;
    cudaGetSymbolAddress((void**)&enc4, g_enc);

    k_encode<<<Bb * Ss, 128>>>((const float4*)batch, (const float4*)mult, enc4);
    k_project<<<(Bb * Ss) / PRT, 128>>>(W, keys);
    k_scan<<<NBLK, 128>>>(keys, U, V, pa, out);
}